// round 1
// baseline (speedup 1.0000x reference)
#include <cuda_runtime.h>
#include <cuda_bf16.h>
#include <cstdint>

#define B_  2
#define S_  2048
#define D_  4096
#define H_  32
#define HD_ 128
#define MTOK (B_*S_)

// ---------------- scratch (allocation-free) ----------------
__device__ float g_q[(size_t)MTOK * D_];
__device__ float g_k[(size_t)MTOK * D_];
__device__ float g_v[(size_t)MTOK * D_];
__device__ float g_a[(size_t)MTOK * D_];

// ---------------- helpers ----------------
__device__ __forceinline__ uint32_t smem_u32(const void* p) {
    return (uint32_t)__cvta_generic_to_shared(p);
}

__device__ __forceinline__ void ldm_x4(uint32_t& r0, uint32_t& r1, uint32_t& r2, uint32_t& r3, uint32_t addr) {
    asm volatile("ldmatrix.sync.aligned.m8n8.x4.shared.b16 {%0,%1,%2,%3}, [%4];"
                 : "=r"(r0), "=r"(r1), "=r"(r2), "=r"(r3) : "r"(addr));
}

__device__ __forceinline__ void ldm_x4_t(uint32_t& r0, uint32_t& r1, uint32_t& r2, uint32_t& r3, uint32_t addr) {
    asm volatile("ldmatrix.sync.aligned.m8n8.x4.trans.shared.b16 {%0,%1,%2,%3}, [%4];"
                 : "=r"(r0), "=r"(r1), "=r"(r2), "=r"(r3) : "r"(addr));
}

__device__ __forceinline__ void mma_bf16(float* c, const uint32_t* a, const uint32_t* b) {
    asm volatile(
        "mma.sync.aligned.m16n8k16.row.col.f32.bf16.bf16.f32 "
        "{%0,%1,%2,%3}, {%4,%5,%6,%7}, {%8,%9}, {%0,%1,%2,%3};"
        : "+f"(c[0]), "+f"(c[1]), "+f"(c[2]), "+f"(c[3])
        : "r"(a[0]), "r"(a[1]), "r"(a[2]), "r"(a[3]), "r"(b[0]), "r"(b[1]));
}

// fp32 pair -> (hi bf16x2, lo bf16x2) packed
__device__ __forceinline__ void split_pack(float a, float b, uint32_t& hi, uint32_t& lo) {
    __nv_bfloat16 ha = __float2bfloat16_rn(a);
    __nv_bfloat16 hb = __float2bfloat16_rn(b);
    __nv_bfloat16 la = __float2bfloat16_rn(a - __bfloat162float(ha));
    __nv_bfloat16 lb = __float2bfloat16_rn(b - __bfloat162float(hb));
    union { __nv_bfloat162 v; uint32_t u; } ch, cl;
    ch.v = __halves2bfloat162(ha, hb);
    cl.v = __halves2bfloat162(la, lb);
    hi = ch.u; lo = cl.u;
}

// ---------------- generic NT GEMM: C[M,N] = A[M,K] * B[N,K]^T ----------------
// bf16x3 split, 128x128x32 block tile, 256 threads, warp tile 64x32.
#define GBM 128
#define GBN 128
#define GBK 32
#define GLD 40   // padded smem row stride (bf16 elems)

__global__ __launch_bounds__(256, 1)
void gemm_nt(const float* __restrict__ A, const float* __restrict__ Bm,
             float* __restrict__ C, int M, int N, int K) {
    __shared__ __align__(16) __nv_bfloat16 sAh[GBM * GLD];
    __shared__ __align__(16) __nv_bfloat16 sAl[GBM * GLD];
    __shared__ __align__(16) __nv_bfloat16 sBh[GBN * GLD];
    __shared__ __align__(16) __nv_bfloat16 sBl[GBN * GLD];

    const int tid = threadIdx.x;
    const int wid = tid >> 5, lane = tid & 31;
    const int wm = wid >> 2, wn = wid & 3;        // 2 x 4 warp grid
    const int m0 = blockIdx.y * GBM, n0 = blockIdx.x * GBN;
    const int lrow = lane & 15, lcol = (lane >> 4) << 3;
    const int g = lane >> 2, tq = lane & 3;

    float acc[4][4][4];
#pragma unroll
    for (int i = 0; i < 4; i++)
#pragma unroll
        for (int j = 0; j < 4; j++)
#pragma unroll
            for (int e = 0; e < 4; e++) acc[i][j][e] = 0.f;

    const int r = tid >> 3;
    const int c4 = (tid & 7) << 2;

    for (int kb = 0; kb < K; kb += GBK) {
#pragma unroll
        for (int p = 0; p < 4; p++) {
            int rr = r + p * 32;
            float4 va = *(const float4*)(A + (size_t)(m0 + rr) * K + kb + c4);
            float4 vb = *(const float4*)(Bm + (size_t)(n0 + rr) * K + kb + c4);
            uint32_t h01, l01, h23, l23;
            split_pack(va.x, va.y, h01, l01);
            split_pack(va.z, va.w, h23, l23);
            uint32_t* pa = (uint32_t*)(sAh + rr * GLD + c4);
            pa[0] = h01; pa[1] = h23;
            uint32_t* pa2 = (uint32_t*)(sAl + rr * GLD + c4);
            pa2[0] = l01; pa2[1] = l23;
            split_pack(vb.x, vb.y, h01, l01);
            split_pack(vb.z, vb.w, h23, l23);
            uint32_t* pb = (uint32_t*)(sBh + rr * GLD + c4);
            pb[0] = h01; pb[1] = h23;
            uint32_t* pb2 = (uint32_t*)(sBl + rr * GLD + c4);
            pb2[0] = l01; pb2[1] = l23;
        }
        __syncthreads();

#pragma unroll
        for (int kc = 0; kc < 2; kc++) {
            uint32_t ah[4][4], al[4][4];
#pragma unroll
            for (int mt = 0; mt < 4; mt++) {
                int row = wm * 64 + mt * 16 + lrow;
                int col = kc * 16 + lcol;
                ldm_x4(ah[mt][0], ah[mt][1], ah[mt][2], ah[mt][3],
                       smem_u32(sAh + row * GLD + col));
                ldm_x4(al[mt][0], al[mt][1], al[mt][2], al[mt][3],
                       smem_u32(sAl + row * GLD + col));
            }
            uint32_t bh[4][2], bl[4][2];
#pragma unroll
            for (int nt2 = 0; nt2 < 2; nt2++) {
                int row = wn * 32 + nt2 * 16 + lrow;
                int col = kc * 16 + lcol;
                uint32_t r0, r1, r2, r3;
                ldm_x4(r0, r1, r2, r3, smem_u32(sBh + row * GLD + col));
                bh[2*nt2][0] = r0; bh[2*nt2][1] = r2;
                bh[2*nt2+1][0] = r1; bh[2*nt2+1][1] = r3;
                ldm_x4(r0, r1, r2, r3, smem_u32(sBl + row * GLD + col));
                bl[2*nt2][0] = r0; bl[2*nt2][1] = r2;
                bl[2*nt2+1][0] = r1; bl[2*nt2+1][1] = r3;
            }
#pragma unroll
            for (int mt = 0; mt < 4; mt++)
#pragma unroll
                for (int nt = 0; nt < 4; nt++) {
                    mma_bf16(acc[mt][nt], ah[mt], bh[nt]);
                    mma_bf16(acc[mt][nt], al[mt], bh[nt]);
                    mma_bf16(acc[mt][nt], ah[mt], bl[nt]);
                }
        }
        __syncthreads();
    }

#pragma unroll
    for (int mt = 0; mt < 4; mt++)
#pragma unroll
        for (int nt = 0; nt < 4; nt++) {
            int row0 = m0 + wm * 64 + mt * 16 + g;
            int col = n0 + wn * 32 + nt * 8 + tq * 2;
            float2 v0 = make_float2(acc[mt][nt][0], acc[mt][nt][1]);
            float2 v1 = make_float2(acc[mt][nt][2], acc[mt][nt][3]);
            *(float2*)(C + (size_t)row0 * N + col) = v0;
            *(float2*)(C + (size_t)(row0 + 8) * N + col) = v1;
        }
}

// ---------------- RoPE ----------------
__global__ void rope_kernel(float* __restrict__ q, float* __restrict__ k,
                            const float* __restrict__ fc, const float* __restrict__ fs) {
    int idx = blockIdx.x * blockDim.x + threadIdx.x;
    const int TOT = B_ * S_ * H_ * (HD_ / 2);
    if (idx >= TOT) return;
    int i  = idx & 63;
    int hh = (idx >> 6) & 31;
    int ss = (idx >> 11) & 2047;
    int bb = idx >> 22;
    float c = fc[ss * 64 + i], sn = fs[ss * 64 + i];
    size_t base = ((size_t)(bb * S_ + ss)) * D_ + hh * HD_ + 2 * i;
    float2 xq = *(float2*)(q + base);
    *(float2*)(q + base) = make_float2(xq.x * c - xq.y * sn, xq.x * sn + xq.y * c);
    float2 xk = *(float2*)(k + base);
    *(float2*)(k + base) = make_float2(xk.x * c - xk.y * sn, xk.x * sn + xk.y * c);
}

// ---------------- flash attention ----------------
// block: 256 thr (8 warps), q-tile 128 rows (16/warp), kv-tile 64, HD=128.
#define ALD 136  // padded smem stride for 128-wide tiles (bf16)

__global__ __launch_bounds__(256, 1)
void attn_kernel(const float* __restrict__ Q, const float* __restrict__ Kt,
                 const float* __restrict__ Vt, float* __restrict__ O) {
    extern __shared__ __align__(16) __nv_bfloat16 smn[];
    __nv_bfloat16* sQh = smn;
    __nv_bfloat16* sQl = sQh + 128 * ALD;
    __nv_bfloat16* sKh = sQl + 128 * ALD;
    __nv_bfloat16* sKl = sKh + 64 * ALD;
    __nv_bfloat16* sVh = sKl + 64 * ALD;
    __nv_bfloat16* sVl = sVh + 64 * ALD;

    const int tid = threadIdx.x;
    const int wid = tid >> 5, lane = tid & 31;
    const int g = lane >> 2, tq = lane & 3;
    const int qt = blockIdx.x, h = blockIdx.y, b = blockIdx.z;
    const int lrow = lane & 15, lcol8 = (lane >> 4) << 3;
    const float scale = 0.08838834764831845f;

    // load Q tile (128 x 128 fp32) -> hi/lo bf16
    {
        int rbase = tid >> 5;
        int c4 = lane << 2;
#pragma unroll
        for (int p = 0; p < 16; p++) {
            int rr = rbase + p * 8;
            float4 vq = *(const float4*)(Q + ((size_t)(b * S_ + qt * 128 + rr)) * D_ + h * HD_ + c4);
            uint32_t h01, l01, h23, l23;
            split_pack(vq.x, vq.y, h01, l01);
            split_pack(vq.z, vq.w, h23, l23);
            uint32_t* ph = (uint32_t*)(sQh + rr * ALD + c4);
            ph[0] = h01; ph[1] = h23;
            uint32_t* pl = (uint32_t*)(sQl + rr * ALD + c4);
            pl[0] = l01; pl[1] = l23;
        }
    }

    float oacc[16][4];
#pragma unroll
    for (int i = 0; i < 16; i++)
#pragma unroll
        for (int e = 0; e < 4; e++) oacc[i][e] = 0.f;
    float sm2[2] = {-1e30f, -1e30f};
    float sl2[2] = {0.f, 0.f};

    const int jmax = 2 * qt + 1;
    for (int j = 0; j <= jmax; ++j) {
        __syncthreads();
        // load K, V tiles (64 x 128)
        {
            int rbase = tid >> 5;
            int c4 = lane << 2;
#pragma unroll
            for (int p = 0; p < 8; p++) {
                int rr = rbase + p * 8;
                size_t goff = ((size_t)(b * S_ + j * 64 + rr)) * D_ + h * HD_ + c4;
                float4 vk = *(const float4*)(Kt + goff);
                float4 vv = *(const float4*)(Vt + goff);
                uint32_t h01, l01, h23, l23;
                split_pack(vk.x, vk.y, h01, l01);
                split_pack(vk.z, vk.w, h23, l23);
                uint32_t* p1 = (uint32_t*)(sKh + rr * ALD + c4); p1[0] = h01; p1[1] = h23;
                uint32_t* p2 = (uint32_t*)(sKl + rr * ALD + c4); p2[0] = l01; p2[1] = l23;
                split_pack(vv.x, vv.y, h01, l01);
                split_pack(vv.z, vv.w, h23, l23);
                uint32_t* p3 = (uint32_t*)(sVh + rr * ALD + c4); p3[0] = h01; p3[1] = h23;
                uint32_t* p4 = (uint32_t*)(sVl + rr * ALD + c4); p4[0] = l01; p4[1] = l23;
            }
        }
        __syncthreads();

        // S = Q K^T  (warp: 16 q-rows x 64 kv)
        float sacc[8][4];
#pragma unroll
        for (int i = 0; i < 8; i++)
#pragma unroll
            for (int e = 0; e < 4; e++) sacc[i][e] = 0.f;

#pragma unroll
        for (int kc = 0; kc < 8; kc++) {
            uint32_t qh[4], ql[4];
            int qrow = wid * 16 + lrow;
            int col = kc * 16 + lcol8;
            ldm_x4(qh[0], qh[1], qh[2], qh[3], smem_u32(sQh + qrow * ALD + col));
            ldm_x4(ql[0], ql[1], ql[2], ql[3], smem_u32(sQl + qrow * ALD + col));
#pragma unroll
            for (int nt2 = 0; nt2 < 4; nt2++) {
                int krow = nt2 * 16 + lrow;
                uint32_t r0, r1, r2, r3, s0, s1, s2, s3;
                ldm_x4(r0, r1, r2, r3, smem_u32(sKh + krow * ALD + col));
                ldm_x4(s0, s1, s2, s3, smem_u32(sKl + krow * ALD + col));
                uint32_t bh0[2] = {r0, r2}, bh1[2] = {r1, r3};
                uint32_t bl0[2] = {s0, s2}, bl1[2] = {s1, s3};
                mma_bf16(sacc[2*nt2], qh, bh0);
                mma_bf16(sacc[2*nt2], ql, bh0);
                mma_bf16(sacc[2*nt2], qh, bl0);
                mma_bf16(sacc[2*nt2+1], qh, bh1);
                mma_bf16(sacc[2*nt2+1], ql, bh1);
                mma_bf16(sacc[2*nt2+1], qh, bl1);
            }
        }

        // scale + causal mask + online softmax
        const int qg0 = qt * 128 + wid * 16 + g;
        const bool need_mask = (j >= 2 * qt);
        float mx0 = -1e30f, mx1 = -1e30f;
#pragma unroll
        for (int nt = 0; nt < 8; nt++) {
            int kg = j * 64 + nt * 8 + tq * 2;
#pragma unroll
            for (int e = 0; e < 4; e++) {
                float sv = sacc[nt][e] * scale;
                int row = (e < 2) ? qg0 : (qg0 + 8);
                int col = kg + (e & 1);
                if (need_mask && col > row) sv = -1e30f;
                sacc[nt][e] = sv;
                if (e < 2) mx0 = fmaxf(mx0, sv); else mx1 = fmaxf(mx1, sv);
            }
        }
        mx0 = fmaxf(mx0, __shfl_xor_sync(0xffffffffu, mx0, 1));
        mx0 = fmaxf(mx0, __shfl_xor_sync(0xffffffffu, mx0, 2));
        mx1 = fmaxf(mx1, __shfl_xor_sync(0xffffffffu, mx1, 1));
        mx1 = fmaxf(mx1, __shfl_xor_sync(0xffffffffu, mx1, 2));

        float mn0 = fmaxf(sm2[0], mx0), mn1 = fmaxf(sm2[1], mx1);
        float al0 = __expf(sm2[0] - mn0), al1 = __expf(sm2[1] - mn1);
        sm2[0] = mn0; sm2[1] = mn1;

        float rs0 = 0.f, rs1 = 0.f;
#pragma unroll
        for (int nt = 0; nt < 8; nt++)
#pragma unroll
            for (int e = 0; e < 4; e++) {
                float pv = __expf(sacc[nt][e] - ((e < 2) ? mn0 : mn1));
                sacc[nt][e] = pv;
                if (e < 2) rs0 += pv; else rs1 += pv;
            }
        rs0 += __shfl_xor_sync(0xffffffffu, rs0, 1);
        rs0 += __shfl_xor_sync(0xffffffffu, rs0, 2);
        rs1 += __shfl_xor_sync(0xffffffffu, rs1, 1);
        rs1 += __shfl_xor_sync(0xffffffffu, rs1, 2);
        sl2[0] = sl2[0] * al0 + rs0;
        sl2[1] = sl2[1] * al1 + rs1;

#pragma unroll
        for (int dt = 0; dt < 16; dt++) {
            oacc[dt][0] *= al0; oacc[dt][1] *= al0;
            oacc[dt][2] *= al1; oacc[dt][3] *= al1;
        }

        // O += P V  (P re-split to bf16 hi/lo, register repack C->A frag)
#pragma unroll
        for (int kc = 0; kc < 4; kc++) {
            uint32_t ph[4], pl[4];
            split_pack(sacc[2*kc][0],   sacc[2*kc][1],   ph[0], pl[0]);
            split_pack(sacc[2*kc][2],   sacc[2*kc][3],   ph[1], pl[1]);
            split_pack(sacc[2*kc+1][0], sacc[2*kc+1][1], ph[2], pl[2]);
            split_pack(sacc[2*kc+1][2], sacc[2*kc+1][3], ph[3], pl[3]);
#pragma unroll
            for (int dt2 = 0; dt2 < 8; dt2++) {
                int vrow = kc * 16 + lrow;
                int col = dt2 * 16 + lcol8;
                uint32_t r0, r1, r2, r3, s0, s1, s2, s3;
                ldm_x4_t(r0, r1, r2, r3, smem_u32(sVh + vrow * ALD + col));
                ldm_x4_t(s0, s1, s2, s3, smem_u32(sVl + vrow * ALD + col));
                uint32_t vh0[2] = {r0, r1}, vh1[2] = {r2, r3};
                uint32_t vl0[2] = {s0, s1}, vl1[2] = {s2, s3};
                mma_bf16(oacc[2*dt2], ph, vh0);
                mma_bf16(oacc[2*dt2], pl, vh0);
                mma_bf16(oacc[2*dt2], ph, vl0);
                mma_bf16(oacc[2*dt2+1], ph, vh1);
                mma_bf16(oacc[2*dt2+1], pl, vh1);
                mma_bf16(oacc[2*dt2+1], ph, vl1);
            }
        }
    }

    // epilogue: normalize + write
    float inv0 = 1.f / sl2[0];
    float inv1 = 1.f / sl2[1];
    int s0r = qt * 128 + wid * 16 + g;
#pragma unroll
    for (int dt = 0; dt < 16; dt++) {
        int col = h * HD_ + dt * 8 + tq * 2;
        float2 v0 = make_float2(oacc[dt][0] * inv0, oacc[dt][1] * inv0);
        float2 v1 = make_float2(oacc[dt][2] * inv1, oacc[dt][3] * inv1);
        *(float2*)(O + ((size_t)(b * S_ + s0r)) * D_ + col) = v0;
        *(float2*)(O + ((size_t)(b * S_ + s0r + 8)) * D_ + col) = v1;
    }
}

// ---------------- launch ----------------
extern "C" void kernel_launch(void* const* d_in, const int* in_sizes, int n_in,
                              void* d_out, int out_size) {
    const float* x  = (const float*)d_in[0];
    const float* fc = (const float*)d_in[1];
    const float* fs = (const float*)d_in[2];
    // d_in[3] = mask (unused: causal mask computed analytically)
    const float* wq = (const float*)d_in[4];
    const float* wk = (const float*)d_in[5];
    const float* wv = (const float*)d_in[6];
    const float* wo = (const float*)d_in[7];
    // d_in[8] = start_pos (always 0)
    float* out = (float*)d_out;

    float *q, *k, *v, *a;
    cudaGetSymbolAddress((void**)&q, g_q);
    cudaGetSymbolAddress((void**)&k, g_k);
    cudaGetSymbolAddress((void**)&v, g_v);
    cudaGetSymbolAddress((void**)&a, g_a);

    dim3 gg(D_ / GBN, MTOK / GBM);
    gemm_nt<<<gg, 256>>>(x, wq, q, MTOK, D_, D_);
    gemm_nt<<<gg, 256>>>(x, wk, k, MTOK, D_, D_);
    gemm_nt<<<gg, 256>>>(x, wv, v, MTOK, D_, D_);

    const int rope_tot = B_ * S_ * H_ * (HD_ / 2);
    rope_kernel<<<(rope_tot + 255) / 256, 256>>>(q, k, fc, fs);

    const int attn_smem = (2 * 128 * ALD + 4 * 64 * ALD) * (int)sizeof(__nv_bfloat16);
    cudaFuncSetAttribute(attn_kernel, cudaFuncAttributeMaxDynamicSharedMemorySize, attn_smem);
    attn_kernel<<<dim3(S_ / 128, H_, B_), 256, attn_smem>>>(q, k, v, a);

    gemm_nt<<<gg, 256>>>(a, wo, out, MTOK, D_, D_);
}

// round 2
// speedup vs baseline: 1.2355x; 1.2355x over previous
#include <cuda_runtime.h>
#include <cuda_bf16.h>
#include <cstdint>

#define B_  2
#define S_  2048
#define D_  4096
#define H_  32
#define HD_ 128
#define MTOK (B_*S_)
#define NELEM ((size_t)MTOK * D_)   // 16,777,216 (same as D_*D_)

// ---------------- scratch (allocation-free) ----------------
__device__ float g_q[NELEM];
__device__ float g_k[NELEM];

__device__ __nv_bfloat16 g_xh[NELEM],  g_xl[NELEM];
__device__ __nv_bfloat16 g_wqh[NELEM], g_wql[NELEM];
__device__ __nv_bfloat16 g_wkh[NELEM], g_wkl[NELEM];
__device__ __nv_bfloat16 g_wvh[NELEM], g_wvl[NELEM];
__device__ __nv_bfloat16 g_woh[NELEM], g_wol[NELEM];
__device__ __nv_bfloat16 g_qh[NELEM],  g_ql[NELEM];
__device__ __nv_bfloat16 g_kh[NELEM],  g_kl[NELEM];
__device__ __nv_bfloat16 g_vh[NELEM],  g_vl[NELEM];
__device__ __nv_bfloat16 g_ah[NELEM],  g_al[NELEM];

// ---------------- helpers ----------------
__device__ __forceinline__ uint32_t smem_u32(const void* p) {
    return (uint32_t)__cvta_generic_to_shared(p);
}

__device__ __forceinline__ void cp16(void* dst, const void* src) {
    asm volatile("cp.async.cg.shared.global [%0], [%1], 16;"
                 :: "r"(smem_u32(dst)), "l"(src) : "memory");
}
__device__ __forceinline__ void cp_commit() {
    asm volatile("cp.async.commit_group;" ::: "memory");
}
template<int N>
__device__ __forceinline__ void cp_wait() {
    asm volatile("cp.async.wait_group %0;" :: "n"(N) : "memory");
}

__device__ __forceinline__ void ldm_x4(uint32_t& r0, uint32_t& r1, uint32_t& r2, uint32_t& r3, uint32_t addr) {
    asm volatile("ldmatrix.sync.aligned.m8n8.x4.shared.b16 {%0,%1,%2,%3}, [%4];"
                 : "=r"(r0), "=r"(r1), "=r"(r2), "=r"(r3) : "r"(addr));
}
__device__ __forceinline__ void ldm_x4_t(uint32_t& r0, uint32_t& r1, uint32_t& r2, uint32_t& r3, uint32_t addr) {
    asm volatile("ldmatrix.sync.aligned.m8n8.x4.trans.shared.b16 {%0,%1,%2,%3}, [%4];"
                 : "=r"(r0), "=r"(r1), "=r"(r2), "=r"(r3) : "r"(addr));
}

__device__ __forceinline__ void mma_bf16(float* c, const uint32_t* a, const uint32_t* b) {
    asm volatile(
        "mma.sync.aligned.m16n8k16.row.col.f32.bf16.bf16.f32 "
        "{%0,%1,%2,%3}, {%4,%5,%6,%7}, {%8,%9}, {%0,%1,%2,%3};"
        : "+f"(c[0]), "+f"(c[1]), "+f"(c[2]), "+f"(c[3])
        : "r"(a[0]), "r"(a[1]), "r"(a[2]), "r"(a[3]), "r"(b[0]), "r"(b[1]));
}

// fp32 pair -> (hi bf16x2, lo bf16x2) packed
__device__ __forceinline__ void split_pack(float a, float b, uint32_t& hi, uint32_t& lo) {
    __nv_bfloat16 ha = __float2bfloat16_rn(a);
    __nv_bfloat16 hb = __float2bfloat16_rn(b);
    __nv_bfloat16 la = __float2bfloat16_rn(a - __bfloat162float(ha));
    __nv_bfloat16 lb = __float2bfloat16_rn(b - __bfloat162float(hb));
    union { __nv_bfloat162 v; uint32_t u; } ch, cl;
    ch.v = __halves2bfloat162(ha, hb);
    cl.v = __halves2bfloat162(la, lb);
    hi = ch.u; lo = cl.u;
}

// ---------------- convert: fp32 -> bf16 hi/lo ----------------
__global__ void cvt_split(const float4* __restrict__ in,
                          uint2* __restrict__ hi, uint2* __restrict__ lo, int n4) {
    int i = blockIdx.x * blockDim.x + threadIdx.x;
    if (i >= n4) return;
    float4 v = in[i];
    uint32_t h01, l01, h23, l23;
    split_pack(v.x, v.y, h01, l01);
    split_pack(v.z, v.w, h23, l23);
    hi[i] = make_uint2(h01, h23);
    lo[i] = make_uint2(l01, l23);
}

// ---------------- GEMM: C[M,N] = A[M,K] * B[N,K]^T (bf16x3, cp.async 3-stage) ----------------
#define GBM 128
#define GBN 128
#define GBK 32
#define GLD 40          // padded smem row stride (bf16)
#define GSTAGES 3
#define GSTAGE_ELEMS (4 * GBM * GLD)    // Ah,Al,Bh,Bl per stage

template<int OUT>   // 0: fp32 C ; 1: bf16 hi/lo C
__global__ __launch_bounds__(256, 1)
void gemm_nt(const __nv_bfloat16* __restrict__ Ahg, const __nv_bfloat16* __restrict__ Alg,
             const __nv_bfloat16* __restrict__ Bhg, const __nv_bfloat16* __restrict__ Blg,
             float* __restrict__ C,
             __nv_bfloat16* __restrict__ Chg, __nv_bfloat16* __restrict__ Clg,
             int M, int N, int K) {
    extern __shared__ __align__(16) __nv_bfloat16 sm[];

    const int tid = threadIdx.x;
    const int wid = tid >> 5, lane = tid & 31;
    const int wm = wid >> 2, wn = wid & 3;
    const int m0 = blockIdx.y * GBM, n0 = blockIdx.x * GBN;
    const int lrow = lane & 15, lcol = (lane >> 4) << 3;
    const int g = lane >> 2, tq = lane & 3;

    float acc[4][4][4];
#pragma unroll
    for (int i = 0; i < 4; i++)
#pragma unroll
        for (int j = 0; j < 4; j++)
#pragma unroll
            for (int e = 0; e < 4; e++) acc[i][j][e] = 0.f;

    const int KT = K / GBK;

    // per-thread load assignment: 2 chunks of 16B per array per stage
    auto load_stage = [&](int kb, int buf) {
        __nv_bfloat16* base = sm + buf * GSTAGE_ELEMS;
#pragma unroll
        for (int p = 0; p < 2; p++) {
            int c = tid + p * 256;
            int row = c >> 2;
            int col8 = (c & 3) << 3;
            size_t ga = (size_t)(m0 + row) * K + kb * GBK + col8;
            size_t gb = (size_t)(n0 + row) * K + kb * GBK + col8;
            cp16(base + 0 * GBM * GLD + row * GLD + col8, Ahg + ga);
            cp16(base + 1 * GBM * GLD + row * GLD + col8, Alg + ga);
            cp16(base + 2 * GBM * GLD + row * GLD + col8, Bhg + gb);
            cp16(base + 3 * GBM * GLD + row * GLD + col8, Blg + gb);
        }
    };

    load_stage(0, 0); cp_commit();
    load_stage(1, 1); cp_commit();

    for (int kb = 0; kb < KT; kb++) {
        int nb = kb + 2;
        if (nb < KT) load_stage(nb, nb % GSTAGES);
        cp_commit();
        cp_wait<2>();
        __syncthreads();

        const __nv_bfloat16* sAh = sm + (kb % GSTAGES) * GSTAGE_ELEMS;
        const __nv_bfloat16* sAl = sAh + GBM * GLD;
        const __nv_bfloat16* sBh = sAl + GBM * GLD;
        const __nv_bfloat16* sBl = sBh + GBM * GLD;

#pragma unroll
        for (int kc = 0; kc < 2; kc++) {
            uint32_t ah[4][4], al[4][4];
#pragma unroll
            for (int mt = 0; mt < 4; mt++) {
                int row = wm * 64 + mt * 16 + lrow;
                int col = kc * 16 + lcol;
                ldm_x4(ah[mt][0], ah[mt][1], ah[mt][2], ah[mt][3],
                       smem_u32(sAh + row * GLD + col));
                ldm_x4(al[mt][0], al[mt][1], al[mt][2], al[mt][3],
                       smem_u32(sAl + row * GLD + col));
            }
            uint32_t bh[4][2], bl[4][2];
#pragma unroll
            for (int nt2 = 0; nt2 < 2; nt2++) {
                int row = wn * 32 + nt2 * 16 + lrow;
                int col = kc * 16 + lcol;
                uint32_t r0, r1, r2, r3;
                ldm_x4(r0, r1, r2, r3, smem_u32(sBh + row * GLD + col));
                bh[2*nt2][0] = r0; bh[2*nt2][1] = r2;
                bh[2*nt2+1][0] = r1; bh[2*nt2+1][1] = r3;
                ldm_x4(r0, r1, r2, r3, smem_u32(sBl + row * GLD + col));
                bl[2*nt2][0] = r0; bl[2*nt2][1] = r2;
                bl[2*nt2+1][0] = r1; bl[2*nt2+1][1] = r3;
            }
#pragma unroll
            for (int mt = 0; mt < 4; mt++)
#pragma unroll
                for (int nt = 0; nt < 4; nt++) {
                    mma_bf16(acc[mt][nt], ah[mt], bh[nt]);
                    mma_bf16(acc[mt][nt], al[mt], bh[nt]);
                    mma_bf16(acc[mt][nt], ah[mt], bl[nt]);
                }
        }
        __syncthreads();
    }

#pragma unroll
    for (int mt = 0; mt < 4; mt++)
#pragma unroll
        for (int nt = 0; nt < 4; nt++) {
            int row0 = m0 + wm * 64 + mt * 16 + g;
            int col = n0 + wn * 32 + nt * 8 + tq * 2;
            if (OUT == 0) {
                *(float2*)(C + (size_t)row0 * N + col) =
                    make_float2(acc[mt][nt][0], acc[mt][nt][1]);
                *(float2*)(C + (size_t)(row0 + 8) * N + col) =
                    make_float2(acc[mt][nt][2], acc[mt][nt][3]);
            } else {
                uint32_t hi, lo;
                split_pack(acc[mt][nt][0], acc[mt][nt][1], hi, lo);
                *(uint32_t*)(Chg + (size_t)row0 * N + col) = hi;
                *(uint32_t*)(Clg + (size_t)row0 * N + col) = lo;
                split_pack(acc[mt][nt][2], acc[mt][nt][3], hi, lo);
                *(uint32_t*)(Chg + (size_t)(row0 + 8) * N + col) = hi;
                *(uint32_t*)(Clg + (size_t)(row0 + 8) * N + col) = lo;
            }
        }
}

// ---------------- RoPE: fp32 q,k -> rotated bf16 hi/lo ----------------
__global__ void rope_split_kernel(const float* __restrict__ q, const float* __restrict__ k,
                                  const float* __restrict__ fc, const float* __restrict__ fs,
                                  __nv_bfloat16* __restrict__ qh, __nv_bfloat16* __restrict__ ql,
                                  __nv_bfloat16* __restrict__ kh, __nv_bfloat16* __restrict__ kl) {
    int idx = blockIdx.x * blockDim.x + threadIdx.x;
    const int TOT = B_ * S_ * H_ * (HD_ / 2);
    if (idx >= TOT) return;
    int i  = idx & 63;
    int hh = (idx >> 6) & 31;
    int ss = (idx >> 11) & 2047;
    int bb = idx >> 22;
    float c = fc[ss * 64 + i], sn = fs[ss * 64 + i];
    size_t base = ((size_t)(bb * S_ + ss)) * D_ + hh * HD_ + 2 * i;
    float2 xq = *(const float2*)(q + base);
    float2 xk = *(const float2*)(k + base);
    float q0 = xq.x * c - xq.y * sn, q1 = xq.x * sn + xq.y * c;
    float k0 = xk.x * c - xk.y * sn, k1 = xk.x * sn + xk.y * c;
    uint32_t hi, lo;
    split_pack(q0, q1, hi, lo);
    *(uint32_t*)(qh + base) = hi; *(uint32_t*)(ql + base) = lo;
    split_pack(k0, k1, hi, lo);
    *(uint32_t*)(kh + base) = hi; *(uint32_t*)(kl + base) = lo;
}

// ---------------- flash attention (bf16 inputs, cp.async, KV double-buffer) ----------------
#define ALD 136
#define AQ_ELEMS (128 * ALD)
#define AKV_ELEMS (64 * ALD)

__global__ __launch_bounds__(256, 1)
void attn_kernel(const __nv_bfloat16* __restrict__ Qh, const __nv_bfloat16* __restrict__ Ql,
                 const __nv_bfloat16* __restrict__ Kh, const __nv_bfloat16* __restrict__ Kl,
                 const __nv_bfloat16* __restrict__ Vh, const __nv_bfloat16* __restrict__ Vl,
                 __nv_bfloat16* __restrict__ Oh, __nv_bfloat16* __restrict__ Ol) {
    extern __shared__ __align__(16) __nv_bfloat16 smn[];
    __nv_bfloat16* sQh = smn;
    __nv_bfloat16* sQl = sQh + AQ_ELEMS;
    __nv_bfloat16* sKV = sQl + AQ_ELEMS;   // [2 stages][Kh,Kl,Vh,Vl][64*ALD]

    const int tid = threadIdx.x;
    const int wid = tid >> 5, lane = tid & 31;
    const int g = lane >> 2, tq = lane & 3;
    const int qt = blockIdx.x, h = blockIdx.y, b = blockIdx.z;
    const int lrow = lane & 15, lcol8 = (lane >> 4) << 3;
    const float scale = 0.08838834764831845f;

    // issue Q tile loads (group 0 together with KV(0))
    {
#pragma unroll
        for (int p = 0; p < 8; p++) {
            int c = tid + p * 256;
            int row = c >> 4;
            int col8 = (c & 15) << 3;
            size_t goff = ((size_t)(b * S_ + qt * 128 + row)) * D_ + h * HD_ + col8;
            cp16(sQh + row * ALD + col8, Qh + goff);
            cp16(sQl + row * ALD + col8, Ql + goff);
        }
    }

    auto load_kv = [&](int j, int buf) {
        __nv_bfloat16* base = sKV + buf * 4 * AKV_ELEMS;
#pragma unroll
        for (int p = 0; p < 4; p++) {
            int c = tid + p * 256;
            int row = c >> 4;
            int col8 = (c & 15) << 3;
            size_t goff = ((size_t)(b * S_ + j * 64 + row)) * D_ + h * HD_ + col8;
            cp16(base + 0 * AKV_ELEMS + row * ALD + col8, Kh + goff);
            cp16(base + 1 * AKV_ELEMS + row * ALD + col8, Kl + goff);
            cp16(base + 2 * AKV_ELEMS + row * ALD + col8, Vh + goff);
            cp16(base + 3 * AKV_ELEMS + row * ALD + col8, Vl + goff);
        }
    };

    const int jmax = 2 * qt + 1;
    load_kv(0, 0); cp_commit();    // group 0 (Q + KV0)

    float oacc[16][4];
#pragma unroll
    for (int i = 0; i < 16; i++)
#pragma unroll
        for (int e = 0; e < 4; e++) oacc[i][e] = 0.f;
    float sm2[2] = {-1e30f, -1e30f};
    float sl2[2] = {0.f, 0.f};

    for (int j = 0; j <= jmax; ++j) {
        if (j + 1 <= jmax) load_kv(j + 1, (j + 1) & 1);
        cp_commit();               // group j+1 (possibly empty)
        cp_wait<1>();
        __syncthreads();

        const __nv_bfloat16* base = sKV + (j & 1) * 4 * AKV_ELEMS;
        const __nv_bfloat16* sKh = base;
        const __nv_bfloat16* sKl = base + 1 * AKV_ELEMS;
        const __nv_bfloat16* sVh = base + 2 * AKV_ELEMS;
        const __nv_bfloat16* sVl = base + 3 * AKV_ELEMS;

        // S = Q K^T
        float sacc[8][4];
#pragma unroll
        for (int i = 0; i < 8; i++)
#pragma unroll
            for (int e = 0; e < 4; e++) sacc[i][e] = 0.f;

#pragma unroll
        for (int kc = 0; kc < 8; kc++) {
            uint32_t qh[4], ql[4];
            int qrow = wid * 16 + lrow;
            int col = kc * 16 + lcol8;
            ldm_x4(qh[0], qh[1], qh[2], qh[3], smem_u32(sQh + qrow * ALD + col));
            ldm_x4(ql[0], ql[1], ql[2], ql[3], smem_u32(sQl + qrow * ALD + col));
#pragma unroll
            for (int nt2 = 0; nt2 < 4; nt2++) {
                int krow = nt2 * 16 + lrow;
                uint32_t r0, r1, r2, r3, s0, s1, s2, s3;
                ldm_x4(r0, r1, r2, r3, smem_u32(sKh + krow * ALD + col));
                ldm_x4(s0, s1, s2, s3, smem_u32(sKl + krow * ALD + col));
                uint32_t bh0[2] = {r0, r2}, bh1[2] = {r1, r3};
                uint32_t bl0[2] = {s0, s2}, bl1[2] = {s1, s3};
                mma_bf16(sacc[2*nt2], qh, bh0);
                mma_bf16(sacc[2*nt2], ql, bh0);
                mma_bf16(sacc[2*nt2], qh, bl0);
                mma_bf16(sacc[2*nt2+1], qh, bh1);
                mma_bf16(sacc[2*nt2+1], ql, bh1);
                mma_bf16(sacc[2*nt2+1], qh, bl1);
            }
        }

        // scale + causal mask + online softmax
        const int qg0 = qt * 128 + wid * 16 + g;
        const bool need_mask = (j >= 2 * qt);
        float mx0 = -1e30f, mx1 = -1e30f;
#pragma unroll
        for (int nt = 0; nt < 8; nt++) {
            int kg = j * 64 + nt * 8 + tq * 2;
#pragma unroll
            for (int e = 0; e < 4; e++) {
                float sv = sacc[nt][e] * scale;
                int row = (e < 2) ? qg0 : (qg0 + 8);
                int col = kg + (e & 1);
                if (need_mask && col > row) sv = -1e30f;
                sacc[nt][e] = sv;
                if (e < 2) mx0 = fmaxf(mx0, sv); else mx1 = fmaxf(mx1, sv);
            }
        }
        mx0 = fmaxf(mx0, __shfl_xor_sync(0xffffffffu, mx0, 1));
        mx0 = fmaxf(mx0, __shfl_xor_sync(0xffffffffu, mx0, 2));
        mx1 = fmaxf(mx1, __shfl_xor_sync(0xffffffffu, mx1, 1));
        mx1 = fmaxf(mx1, __shfl_xor_sync(0xffffffffu, mx1, 2));

        float mn0 = fmaxf(sm2[0], mx0), mn1 = fmaxf(sm2[1], mx1);
        float al0 = __expf(sm2[0] - mn0), al1 = __expf(sm2[1] - mn1);
        sm2[0] = mn0; sm2[1] = mn1;

        float rs0 = 0.f, rs1 = 0.f;
#pragma unroll
        for (int nt = 0; nt < 8; nt++)
#pragma unroll
            for (int e = 0; e < 4; e++) {
                float pv = __expf(sacc[nt][e] - ((e < 2) ? mn0 : mn1));
                sacc[nt][e] = pv;
                if (e < 2) rs0 += pv; else rs1 += pv;
            }
        rs0 += __shfl_xor_sync(0xffffffffu, rs0, 1);
        rs0 += __shfl_xor_sync(0xffffffffu, rs0, 2);
        rs1 += __shfl_xor_sync(0xffffffffu, rs1, 1);
        rs1 += __shfl_xor_sync(0xffffffffu, rs1, 2);
        sl2[0] = sl2[0] * al0 + rs0;
        sl2[1] = sl2[1] * al1 + rs1;

#pragma unroll
        for (int dt = 0; dt < 16; dt++) {
            oacc[dt][0] *= al0; oacc[dt][1] *= al0;
            oacc[dt][2] *= al1; oacc[dt][3] *= al1;
        }

        // O += P V
#pragma unroll
        for (int kc = 0; kc < 4; kc++) {
            uint32_t ph[4], pl[4];
            split_pack(sacc[2*kc][0],   sacc[2*kc][1],   ph[0], pl[0]);
            split_pack(sacc[2*kc][2],   sacc[2*kc][3],   ph[1], pl[1]);
            split_pack(sacc[2*kc+1][0], sacc[2*kc+1][1], ph[2], pl[2]);
            split_pack(sacc[2*kc+1][2], sacc[2*kc+1][3], ph[3], pl[3]);
#pragma unroll
            for (int dt2 = 0; dt2 < 8; dt2++) {
                int vrow = kc * 16 + lrow;
                int col = dt2 * 16 + lcol8;
                uint32_t r0, r1, r2, r3, s0, s1, s2, s3;
                ldm_x4_t(r0, r1, r2, r3, smem_u32(sVh + vrow * ALD + col));
                ldm_x4_t(s0, s1, s2, s3, smem_u32(sVl + vrow * ALD + col));
                uint32_t vh0[2] = {r0, r1}, vh1[2] = {r2, r3};
                uint32_t vl0[2] = {s0, s1}, vl1[2] = {s2, s3};
                mma_bf16(oacc[2*dt2], ph, vh0);
                mma_bf16(oacc[2*dt2], pl, vh0);
                mma_bf16(oacc[2*dt2], ph, vl0);
                mma_bf16(oacc[2*dt2+1], ph, vh1);
                mma_bf16(oacc[2*dt2+1], pl, vh1);
                mma_bf16(oacc[2*dt2+1], ph, vl1);
            }
        }
        __syncthreads();
    }

    // epilogue: normalize + write bf16 hi/lo
    float inv0 = 1.f / sl2[0];
    float inv1 = 1.f / sl2[1];
    int s0r = qt * 128 + wid * 16 + g;
#pragma unroll
    for (int dt = 0; dt < 16; dt++) {
        int col = h * HD_ + dt * 8 + tq * 2;
        uint32_t hi, lo;
        split_pack(oacc[dt][0] * inv0, oacc[dt][1] * inv0, hi, lo);
        *(uint32_t*)(Oh + ((size_t)(b * S_ + s0r)) * D_ + col) = hi;
        *(uint32_t*)(Ol + ((size_t)(b * S_ + s0r)) * D_ + col) = lo;
        split_pack(oacc[dt][2] * inv1, oacc[dt][3] * inv1, hi, lo);
        *(uint32_t*)(Oh + ((size_t)(b * S_ + s0r + 8)) * D_ + col) = hi;
        *(uint32_t*)(Ol + ((size_t)(b * S_ + s0r + 8)) * D_ + col) = lo;
    }
}

// ---------------- launch ----------------
extern "C" void kernel_launch(void* const* d_in, const int* in_sizes, int n_in,
                              void* d_out, int out_size) {
    const float* x  = (const float*)d_in[0];
    const float* fc = (const float*)d_in[1];
    const float* fs = (const float*)d_in[2];
    const float* wq = (const float*)d_in[4];
    const float* wk = (const float*)d_in[5];
    const float* wv = (const float*)d_in[6];
    const float* wo = (const float*)d_in[7];
    float* out = (float*)d_out;

    float *q, *k;
    cudaGetSymbolAddress((void**)&q, g_q);
    cudaGetSymbolAddress((void**)&k, g_k);
    __nv_bfloat16 *xh, *xl, *wqh, *wql, *wkh, *wkl, *wvh, *wvl, *woh, *wol;
    __nv_bfloat16 *qh, *ql, *kh, *kl, *vh, *vl, *ah, *al;
    cudaGetSymbolAddress((void**)&xh, g_xh);   cudaGetSymbolAddress((void**)&xl, g_xl);
    cudaGetSymbolAddress((void**)&wqh, g_wqh); cudaGetSymbolAddress((void**)&wql, g_wql);
    cudaGetSymbolAddress((void**)&wkh, g_wkh); cudaGetSymbolAddress((void**)&wkl, g_wkl);
    cudaGetSymbolAddress((void**)&wvh, g_wvh); cudaGetSymbolAddress((void**)&wvl, g_wvl);
    cudaGetSymbolAddress((void**)&woh, g_woh); cudaGetSymbolAddress((void**)&wol, g_wol);
    cudaGetSymbolAddress((void**)&qh, g_qh);   cudaGetSymbolAddress((void**)&ql, g_ql);
    cudaGetSymbolAddress((void**)&kh, g_kh);   cudaGetSymbolAddress((void**)&kl, g_kl);
    cudaGetSymbolAddress((void**)&vh, g_vh);   cudaGetSymbolAddress((void**)&vl, g_vl);
    cudaGetSymbolAddress((void**)&ah, g_ah);   cudaGetSymbolAddress((void**)&al, g_al);

    const int n4 = (int)(NELEM / 4);
    const int cvb = (n4 + 255) / 256;
    cvt_split<<<cvb, 256>>>((const float4*)x,  (uint2*)xh,  (uint2*)xl,  n4);
    cvt_split<<<cvb, 256>>>((const float4*)wq, (uint2*)wqh, (uint2*)wql, n4);
    cvt_split<<<cvb, 256>>>((const float4*)wk, (uint2*)wkh, (uint2*)wkl, n4);
    cvt_split<<<cvb, 256>>>((const float4*)wv, (uint2*)wvh, (uint2*)wvl, n4);
    cvt_split<<<cvb, 256>>>((const float4*)wo, (uint2*)woh, (uint2*)wol, n4);

    const int gemm_smem = GSTAGES * GSTAGE_ELEMS * (int)sizeof(__nv_bfloat16);
    cudaFuncSetAttribute(gemm_nt<0>, cudaFuncAttributeMaxDynamicSharedMemorySize, gemm_smem);
    cudaFuncSetAttribute(gemm_nt<1>, cudaFuncAttributeMaxDynamicSharedMemorySize, gemm_smem);

    dim3 gg(D_ / GBN, MTOK / GBM);
    gemm_nt<0><<<gg, 256, gemm_smem>>>(xh, xl, wqh, wql, q, nullptr, nullptr, MTOK, D_, D_);
    gemm_nt<0><<<gg, 256, gemm_smem>>>(xh, xl, wkh, wkl, k, nullptr, nullptr, MTOK, D_, D_);
    gemm_nt<1><<<gg, 256, gemm_smem>>>(xh, xl, wvh, wvl, nullptr, vh, vl, MTOK, D_, D_);

    const int rope_tot = B_ * S_ * H_ * (HD_ / 2);
    rope_split_kernel<<<(rope_tot + 255) / 256, 256>>>(q, k, fc, fs, qh, ql, kh, kl);

    const int attn_smem = (2 * AQ_ELEMS + 2 * 4 * AKV_ELEMS) * (int)sizeof(__nv_bfloat16);
    cudaFuncSetAttribute(attn_kernel, cudaFuncAttributeMaxDynamicSharedMemorySize, attn_smem);
    attn_kernel<<<dim3(S_ / 128, H_, B_), 256, attn_smem>>>(qh, ql, kh, kl, vh, vl, ah, al);

    gemm_nt<0><<<gg, 256, gemm_smem>>>(ah, al, woh, wol, out, nullptr, nullptr, MTOK, D_, D_);
}